// round 7
// baseline (speedup 1.0000x reference)
#include <cuda_runtime.h>

#define NUSERS 100000
#define NITEMS 50000
#define NNODES 150000
#define DIM 64
#define NEDGES 2000000

// Per-node state, float4-packed (DIM=64 -> 16 float4 per node).
__device__ float4 g_emb[NNODES * 16];
__device__ float4 g_next[NNODES * 16];
__device__ float4 g_acc[NNODES * 16];

// 1 if edge_index buffer holds int64 values, 0 if int32.
__device__ int g_ei_is64;

// ---------------------------------------------------------------------------
// probe: detect edge_index element width. If the buffer is int64, every odd
// int32 word is the (zero) high half of a small non-negative index. With
// genuine int32 data, odd words are random indices in [0,150000) — the
// probability 16 of them are all zero is ~(1/150000)^16.
// ---------------------------------------------------------------------------
__global__ void probe_kernel(const int* __restrict__ ei32) {
    if (blockIdx.x != 0 || threadIdx.x != 0) return;
    int all_zero = 1;
    #pragma unroll
    for (int k = 0; k < 16; k++) {
        if (ei32[2 * k + 1] != 0) all_zero = 0;
    }
    g_ei_is64 = all_zero;
}

// ---------------------------------------------------------------------------
// init: emb = concat(users, items); acc = emb; next = 0.
// Also writes the pass-through copies (outputs 2 and 4) into d_out.
// out layout (floats): [users_final U*D][users U*D][items_final I*D][items I*D]
// ---------------------------------------------------------------------------
__global__ void init_kernel(const float4* __restrict__ users,
                            const float4* __restrict__ items,
                            float4* __restrict__ out) {
    int i = blockIdx.x * blockDim.x + threadIdx.x;
    if (i >= NNODES * 16) return;
    float4 v;
    if (i < NUSERS * 16) {
        v = users[i];
        out[NUSERS * 16 + i] = v;                       // emb_users copy
    } else {
        int j = i - NUSERS * 16;
        v = items[j];
        out[2 * NUSERS * 16 + NITEMS * 16 + j] = v;     // emb_items copy
    }
    g_emb[i] = v;
    g_acc[i] = v;
    g_next[i] = make_float4(0.f, 0.f, 0.f, 0.f);
}

// ---------------------------------------------------------------------------
// scatter: for each edge e, next[dst] += w[e] * emb[src]
// 16 threads per edge, one float4 each. Vectorized red.global (no return).
// Index width selected at runtime via g_ei_is64 (uniform branch).
// ---------------------------------------------------------------------------
__global__ void scatter_kernel(const void* __restrict__ ei_raw,
                               const float* __restrict__ w) {
    int t = blockIdx.x * blockDim.x + threadIdx.x;
    int e = t >> 4;
    if (e >= NEDGES) return;
    int lane = t & 15;

    int s, d;
    if (g_ei_is64) {
        const long long* ei = (const long long*)ei_raw;
        s = (int)__ldg(&ei[e]);
        d = (int)__ldg(&ei[NEDGES + e]);
    } else {
        const int* ei = (const int*)ei_raw;
        s = __ldg(&ei[e]);
        d = __ldg(&ei[NEDGES + e]);
    }
    float wt = __ldg(&w[e]);

    // Defensive guard: corrupt indices fail via rel_err, not IMA.
    if ((unsigned)s >= NNODES || (unsigned)d >= NNODES) return;

    float4 v = __ldg(&g_emb[s * 16 + lane]);
    float4* p = &g_next[d * 16 + lane];
    asm volatile("red.global.add.v4.f32 [%0], {%1, %2, %3, %4};"
                 :: "l"(p), "f"(v.x * wt), "f"(v.y * wt),
                    "f"(v.z * wt), "f"(v.w * wt)
                 : "memory");
}

// ---------------------------------------------------------------------------
// relu + accumulate: emb = relu(next); acc += emb; next = 0 (for next layer)
// ---------------------------------------------------------------------------
__global__ void reluacc_kernel() {
    int i = blockIdx.x * blockDim.x + threadIdx.x;
    if (i >= NNODES * 16) return;
    float4 x = g_next[i];
    x.x = fmaxf(x.x, 0.f);
    x.y = fmaxf(x.y, 0.f);
    x.z = fmaxf(x.z, 0.f);
    x.w = fmaxf(x.w, 0.f);
    g_emb[i] = x;
    float4 a = g_acc[i];
    a.x += x.x; a.y += x.y; a.z += x.z; a.w += x.w;
    g_acc[i] = a;
    g_next[i] = make_float4(0.f, 0.f, 0.f, 0.f);
}

// ---------------------------------------------------------------------------
// final: out_final[n, j] = sum_d (acc[n, d] / 3) * W[j, d] + b[j]
// 4 rows per 256-thread block; W transposed into padded shared.
// ---------------------------------------------------------------------------
__global__ void final_kernel(const float* __restrict__ Wm,
                             const float* __restrict__ bias,
                             float* __restrict__ out) {
    __shared__ float Wt[DIM][DIM + 1];   // Wt[d][j] = W[j][d]
    __shared__ float rowS[4][DIM];

    int tid = threadIdx.x;
    // cooperative transpose load of W (64x64)
    for (int k = tid; k < DIM * DIM; k += 256) {
        int j = k / DIM, d = k % DIM;
        Wt[d][j] = Wm[k];
    }

    int r = tid >> 6;          // 0..3 local row
    int j = tid & 63;          // output column
    int row = blockIdx.x * 4 + r;

    const float* accF = (const float*)g_acc;
    rowS[r][j] = accF[row * DIM + j] * (1.0f / 3.0f);
    __syncthreads();

    float sum = bias[j];
    #pragma unroll
    for (int d = 0; d < DIM; d++) {
        sum += rowS[r][d] * Wt[d][j];
    }

    float* dst;
    if (row < NUSERS) {
        dst = out + (size_t)row * DIM;                            // users_final
    } else {
        dst = out + (size_t)2 * NUSERS * DIM + (size_t)(row - NUSERS) * DIM; // items_final
    }
    dst[j] = sum;
}

// ---------------------------------------------------------------------------
extern "C" void kernel_launch(void* const* d_in, const int* in_sizes, int n_in,
                              void* d_out, int out_size) {
    const void*   ei    = d_in[0];                    // edge_index [2, E] (int32 or int64)
    const float*  w     = (const float*)d_in[1];      // edge_weight [E]
    const float4* users = (const float4*)d_in[2];     // [U, 64]
    const float4* items = (const float4*)d_in[3];     // [I, 64]
    const float*  Wm    = (const float*)d_in[4];      // [64, 64]
    const float*  bias  = (const float*)d_in[5];      // [64]
    float* out = (float*)d_out;

    probe_kernel<<<1, 32>>>((const int*)ei);

    const int nodeThreads = NNODES * 16;
    init_kernel<<<(nodeThreads + 255) / 256, 256>>>(users, items, (float4*)out);

    for (int layer = 0; layer < 2; layer++) {
        scatter_kernel<<<(NEDGES * 16 + 255) / 256, 256>>>(ei, w);
        reluacc_kernel<<<(nodeThreads + 255) / 256, 256>>>();
    }

    final_kernel<<<NNODES / 4, 256>>>(Wm, bias, out);
}

// round 14
// speedup vs baseline: 1.4894x; 1.4894x over previous
#include <cuda_runtime.h>

#define NUSERS 100000
#define NITEMS 50000
#define NNODES 150000
#define DIM 64
#define NEDGES 2000000
#define SCAN_B 1024
#define NBLK ((NNODES + SCAN_B - 1) / SCAN_B)   // 147

// Node state (ping-pong emb + residual acc), float4-packed.
__device__ float4 g_emb_a[NNODES * 16];
__device__ float4 g_emb_b[NNODES * 16];
__device__ float4 g_acc[NNODES * 16];

// CSR build state.
__device__ int  g_deg[NNODES];
__device__ int  g_rowptr[NNODES + 1];
__device__ int  g_cursor[NNODES];
__device__ int  g_blocksums[NBLK];
__device__ int  g_blockoffs[NBLK];
__device__ int2 g_adj[NEDGES];        // (src, weight-bits)

__device__ int g_ei_is64;             // edge_index element width flag

// ---------------------------------------------------------------------------
// probe: int64 edge_index read as int32 pairs has all-zero odd words
// (indices < 150000, non-negative). Genuine int32 data: P(16 zeros) ~ 0.
// ---------------------------------------------------------------------------
__global__ void probe_kernel(const int* __restrict__ ei32) {
    if (blockIdx.x != 0 || threadIdx.x != 0) return;
    int all_zero = 1;
    #pragma unroll
    for (int k = 0; k < 16; k++)
        if (ei32[2 * k + 1] != 0) all_zero = 0;
    g_ei_is64 = all_zero;
}

__device__ __forceinline__ void load_edge(const void* ei_raw, int e,
                                          int& s, int& d) {
    if (g_ei_is64) {
        const long long* ei = (const long long*)ei_raw;
        s = (int)__ldg(&ei[e]);
        d = (int)__ldg(&ei[NEDGES + e]);
    } else {
        const int* ei = (const int*)ei_raw;
        s = __ldg(&ei[e]);
        d = __ldg(&ei[NEDGES + e]);
    }
}

// ---------------------------------------------------------------------------
// init: emb_a = concat(users, items); acc = emb_a; deg = 0; passthrough copies.
// out layout (floats): [users_final U*D][users U*D][items_final I*D][items I*D]
// ---------------------------------------------------------------------------
__global__ void init_kernel(const float4* __restrict__ users,
                            const float4* __restrict__ items,
                            float4* __restrict__ out) {
    int i = blockIdx.x * blockDim.x + threadIdx.x;
    if (i < NNODES) g_deg[i] = 0;
    if (i >= NNODES * 16) return;
    float4 v;
    if (i < NUSERS * 16) {
        v = users[i];
        out[NUSERS * 16 + i] = v;                       // emb_users copy
    } else {
        int j = i - NUSERS * 16;
        v = items[j];
        out[2 * NUSERS * 16 + NITEMS * 16 + j] = v;     // emb_items copy
    }
    g_emb_a[i] = v;
    g_acc[i] = v;
}

// ---------------------------------------------------------------------------
// CSR build: count -> scan (3 kernels) -> fill
// ---------------------------------------------------------------------------
__global__ void count_kernel(const void* __restrict__ ei_raw) {
    int e = blockIdx.x * blockDim.x + threadIdx.x;
    if (e >= NEDGES) return;
    int s, d;
    load_edge(ei_raw, e, s, d);
    if ((unsigned)d >= NNODES) return;
    atomicAdd(&g_deg[d], 1);
}

__global__ void scanA_kernel() {
    __shared__ int sh[SCAN_B];
    int t = threadIdx.x;
    int i = blockIdx.x * SCAN_B + t;
    int v = (i < NNODES) ? g_deg[i] : 0;
    sh[t] = v;
    __syncthreads();
    #pragma unroll
    for (int off = 1; off < SCAN_B; off <<= 1) {
        int x = (t >= off) ? sh[t - off] : 0;
        __syncthreads();
        if (t >= off) sh[t] += x;
        __syncthreads();
    }
    if (i < NNODES) g_rowptr[i] = sh[t] - v;           // exclusive (local)
    if (t == SCAN_B - 1) g_blocksums[blockIdx.x] = sh[t];
}

__global__ void scanB_kernel() {
    __shared__ int sh[256];
    int t = threadIdx.x;
    int v = (t < NBLK) ? g_blocksums[t] : 0;
    sh[t] = v;
    __syncthreads();
    #pragma unroll
    for (int off = 1; off < 256; off <<= 1) {
        int x = (t >= off) ? sh[t - off] : 0;
        __syncthreads();
        if (t >= off) sh[t] += x;
        __syncthreads();
    }
    if (t < NBLK) g_blockoffs[t] = sh[t] - v;          // exclusive over blocks
    if (t == 0) g_rowptr[NNODES] = NEDGES;
}

__global__ void scanC_kernel() {
    int i = blockIdx.x * blockDim.x + threadIdx.x;
    if (i >= NNODES) return;
    int r = g_rowptr[i] + g_blockoffs[i >> 10];
    g_rowptr[i] = r;
    g_cursor[i] = r;
}

__global__ void fill_kernel(const void* __restrict__ ei_raw,
                            const float* __restrict__ w) {
    int e = blockIdx.x * blockDim.x + threadIdx.x;
    if (e >= NEDGES) return;
    int s, d;
    load_edge(ei_raw, e, s, d);
    float wt = __ldg(&w[e]);
    if ((unsigned)s >= NNODES || (unsigned)d >= NNODES) return;
    int pos = atomicAdd(&g_cursor[d], 1);
    g_adj[pos] = make_int2(s, __float_as_int(wt));
}

// ---------------------------------------------------------------------------
// gather layer: for each node n, sum_{e in adj(n)} w_e * semb[src_e];
// relu; write demb[n]; acc[n] += relu'd value.  16 threads/node, float4 each.
// dir==0: emb_a -> emb_b ; dir==1: emb_b -> emb_a.
// 4-way unroll: 4 independent adj loads + 4 independent gathers in flight
// per thread per iteration (MLP against the ~250cyc L2 latency).
// ---------------------------------------------------------------------------
__global__ void gather_kernel(int dir) {
    int t = blockIdx.x * blockDim.x + threadIdx.x;
    int node = t >> 4;
    if (node >= NNODES) return;
    int lane = t & 15;

    const float4* semb = dir ? g_emb_b : g_emb_a;
    float4*       demb = dir ? g_emb_a : g_emb_b;

    int beg = __ldg(&g_rowptr[node]);
    int end = __ldg(&g_rowptr[node + 1]);

    float4 sum = make_float4(0.f, 0.f, 0.f, 0.f);
    int i = beg;
    for (; i + 3 < end; i += 4) {
        int2 a0 = __ldg(&g_adj[i]);
        int2 a1 = __ldg(&g_adj[i + 1]);
        int2 a2 = __ldg(&g_adj[i + 2]);
        int2 a3 = __ldg(&g_adj[i + 3]);
        float4 v0 = __ldg(&semb[a0.x * 16 + lane]);
        float4 v1 = __ldg(&semb[a1.x * 16 + lane]);
        float4 v2 = __ldg(&semb[a2.x * 16 + lane]);
        float4 v3 = __ldg(&semb[a3.x * 16 + lane]);
        float w0 = __int_as_float(a0.y);
        float w1 = __int_as_float(a1.y);
        float w2 = __int_as_float(a2.y);
        float w3 = __int_as_float(a3.y);
        sum.x = fmaf(v0.x, w0, sum.x); sum.y = fmaf(v0.y, w0, sum.y);
        sum.z = fmaf(v0.z, w0, sum.z); sum.w = fmaf(v0.w, w0, sum.w);
        sum.x = fmaf(v1.x, w1, sum.x); sum.y = fmaf(v1.y, w1, sum.y);
        sum.z = fmaf(v1.z, w1, sum.z); sum.w = fmaf(v1.w, w1, sum.w);
        sum.x = fmaf(v2.x, w2, sum.x); sum.y = fmaf(v2.y, w2, sum.y);
        sum.z = fmaf(v2.z, w2, sum.z); sum.w = fmaf(v2.w, w2, sum.w);
        sum.x = fmaf(v3.x, w3, sum.x); sum.y = fmaf(v3.y, w3, sum.y);
        sum.z = fmaf(v3.z, w3, sum.z); sum.w = fmaf(v3.w, w3, sum.w);
    }
    for (; i < end; i++) {
        int2 a0 = __ldg(&g_adj[i]);
        float4 v0 = __ldg(&semb[a0.x * 16 + lane]);
        float w0 = __int_as_float(a0.y);
        sum.x = fmaf(v0.x, w0, sum.x); sum.y = fmaf(v0.y, w0, sum.y);
        sum.z = fmaf(v0.z, w0, sum.z); sum.w = fmaf(v0.w, w0, sum.w);
    }

    // fused relu + residual accumulate
    sum.x = fmaxf(sum.x, 0.f); sum.y = fmaxf(sum.y, 0.f);
    sum.z = fmaxf(sum.z, 0.f); sum.w = fmaxf(sum.w, 0.f);
    int idx = node * 16 + lane;
    demb[idx] = sum;
    float4 a = g_acc[idx];
    a.x += sum.x; a.y += sum.y; a.z += sum.z; a.w += sum.w;
    g_acc[idx] = a;
}

// ---------------------------------------------------------------------------
// final: out_final[n, j] = sum_d (acc[n, d] / 3) * W[j, d] + b[j]
// ---------------------------------------------------------------------------
__global__ void final_kernel(const float* __restrict__ Wm,
                             const float* __restrict__ bias,
                             float* __restrict__ out) {
    __shared__ float Wt[DIM][DIM + 1];
    __shared__ float rowS[4][DIM];

    int tid = threadIdx.x;
    for (int k = tid; k < DIM * DIM; k += 256) {
        int j = k / DIM, d = k % DIM;
        Wt[d][j] = Wm[k];
    }

    int r = tid >> 6;
    int j = tid & 63;
    int row = blockIdx.x * 4 + r;

    const float* accF = (const float*)g_acc;
    rowS[r][j] = accF[row * DIM + j] * (1.0f / 3.0f);
    __syncthreads();

    float sum = bias[j];
    #pragma unroll
    for (int d = 0; d < DIM; d++)
        sum += rowS[r][d] * Wt[d][j];

    float* dst;
    if (row < NUSERS) {
        dst = out + (size_t)row * DIM;
    } else {
        dst = out + (size_t)2 * NUSERS * DIM + (size_t)(row - NUSERS) * DIM;
    }
    dst[j] = sum;
}

// ---------------------------------------------------------------------------
extern "C" void kernel_launch(void* const* d_in, const int* in_sizes, int n_in,
                              void* d_out, int out_size) {
    const void*   ei    = d_in[0];
    const float*  w     = (const float*)d_in[1];
    const float4* users = (const float4*)d_in[2];
    const float4* items = (const float4*)d_in[3];
    const float*  Wm    = (const float*)d_in[4];
    const float*  bias  = (const float*)d_in[5];
    float* out = (float*)d_out;

    probe_kernel<<<1, 32>>>((const int*)ei);

    const int nodeThreads = NNODES * 16;
    init_kernel<<<(nodeThreads + 255) / 256, 256>>>(users, items, (float4*)out);

    // CSR build
    count_kernel<<<(NEDGES + 255) / 256, 256>>>(ei);
    scanA_kernel<<<NBLK, SCAN_B>>>();
    scanB_kernel<<<1, 256>>>();
    scanC_kernel<<<(NNODES + 255) / 256, 256>>>();
    fill_kernel<<<(NEDGES + 255) / 256, 256>>>(ei, w);

    // Two propagation layers (gather + fused relu/acc)
    gather_kernel<<<(nodeThreads + 255) / 256, 256>>>(0);   // emb_a -> emb_b
    gather_kernel<<<(nodeThreads + 255) / 256, 256>>>(1);   // emb_b -> emb_a

    final_kernel<<<NNODES / 4, 256>>>(Wm, bias, out);
}

// round 15
// speedup vs baseline: 1.8855x; 1.2660x over previous
#include <cuda_runtime.h>

#define NUSERS 100000
#define NITEMS 50000
#define NNODES 150000
#define DIM 64
#define NEDGES 2000000
#define SCAN_B 1024
#define NBLK ((NNODES + SCAN_B - 1) / SCAN_B)   // 147

// Node state, float4-packed.
__device__ float4 g_emb_a[NNODES * 16];
__device__ float4 g_emb_b[NNODES * 16];
__device__ float4 g_acc[NNODES * 16];

// CSR build state.
__device__ int  g_deg[NNODES];
__device__ int  g_rowptr[NNODES + 1];
__device__ int  g_cursor[NNODES];
__device__ int  g_blocksums[NBLK];
__device__ int  g_blockoffs[NBLK];
__device__ int2 g_adj[NEDGES];        // (src, weight-bits)

__device__ int g_ei_is64;

// ---------------------------------------------------------------------------
// probe: zero g_deg grid-wide; thread (0,0) detects edge_index element width.
// int64 data read as int32 pairs has all-zero odd (high-half) words.
// ---------------------------------------------------------------------------
__global__ void probe_kernel(const int* __restrict__ ei32) {
    int i = blockIdx.x * blockDim.x + threadIdx.x;
    if (i < NNODES) g_deg[i] = 0;
    if (blockIdx.x == 0 && threadIdx.x == 0) {
        int all_zero = 1;
        #pragma unroll
        for (int k = 0; k < 16; k++)
            if (ei32[2 * k + 1] != 0) all_zero = 0;
        g_ei_is64 = all_zero;
    }
}

__device__ __forceinline__ void load_edge(const void* ei_raw, int e,
                                          int& s, int& d) {
    if (g_ei_is64) {
        const long long* ei = (const long long*)ei_raw;
        s = (int)__ldg(&ei[e]);
        d = (int)__ldg(&ei[NEDGES + e]);
    } else {
        const int* ei = (const int*)ei_raw;
        s = __ldg(&ei[e]);
        d = __ldg(&ei[NEDGES + e]);
    }
}

__device__ __forceinline__ int load_dst(const void* ei_raw, int e) {
    if (g_ei_is64) {
        const long long* ei = (const long long*)ei_raw;
        return (int)__ldg(&ei[NEDGES + e]);
    } else {
        const int* ei = (const int*)ei_raw;
        return __ldg(&ei[NEDGES + e]);
    }
}

// ---------------------------------------------------------------------------
// init + count fused: emb_a = concat(users, items); acc = emb_a;
// passthrough copies; and per-edge degree count (g_deg zeroed by probe).
// out layout (floats): [users_final U*D][users U*D][items_final I*D][items I*D]
// ---------------------------------------------------------------------------
__global__ void init_count_kernel(const float4* __restrict__ users,
                                  const float4* __restrict__ items,
                                  float4* __restrict__ out,
                                  const void* __restrict__ ei_raw) {
    int i = blockIdx.x * blockDim.x + threadIdx.x;

    if (i < NEDGES) {
        int d = load_dst(ei_raw, i);
        if ((unsigned)d < NNODES) atomicAdd(&g_deg[d], 1);
    }

    if (i >= NNODES * 16) return;
    float4 v;
    if (i < NUSERS * 16) {
        v = users[i];
        out[NUSERS * 16 + i] = v;                       // emb_users copy
    } else {
        int j = i - NUSERS * 16;
        v = items[j];
        out[2 * NUSERS * 16 + NITEMS * 16 + j] = v;     // emb_items copy
    }
    g_emb_a[i] = v;
    g_acc[i] = v;
}

// ---------------------------------------------------------------------------
// scan (3 kernels) -> fill
// ---------------------------------------------------------------------------
__global__ void scanA_kernel() {
    __shared__ int sh[SCAN_B];
    int t = threadIdx.x;
    int i = blockIdx.x * SCAN_B + t;
    int v = (i < NNODES) ? g_deg[i] : 0;
    sh[t] = v;
    __syncthreads();
    #pragma unroll
    for (int off = 1; off < SCAN_B; off <<= 1) {
        int x = (t >= off) ? sh[t - off] : 0;
        __syncthreads();
        if (t >= off) sh[t] += x;
        __syncthreads();
    }
    if (i < NNODES) g_rowptr[i] = sh[t] - v;           // exclusive (local)
    if (t == SCAN_B - 1) g_blocksums[blockIdx.x] = sh[t];
}

__global__ void scanB_kernel() {
    __shared__ int sh[256];
    int t = threadIdx.x;
    int v = (t < NBLK) ? g_blocksums[t] : 0;
    sh[t] = v;
    __syncthreads();
    #pragma unroll
    for (int off = 1; off < 256; off <<= 1) {
        int x = (t >= off) ? sh[t - off] : 0;
        __syncthreads();
        if (t >= off) sh[t] += x;
        __syncthreads();
    }
    if (t < NBLK) g_blockoffs[t] = sh[t] - v;          // exclusive over blocks
    if (t == 0) g_rowptr[NNODES] = NEDGES;
}

__global__ void scanC_kernel() {
    int i = blockIdx.x * blockDim.x + threadIdx.x;
    if (i >= NNODES) return;
    int r = g_rowptr[i] + g_blockoffs[i >> 10];
    g_rowptr[i] = r;
    g_cursor[i] = r;
}

__global__ void fill_kernel(const void* __restrict__ ei_raw,
                            const float* __restrict__ w) {
    int e = blockIdx.x * blockDim.x + threadIdx.x;
    if (e >= NEDGES) return;
    int s, d;
    load_edge(ei_raw, e, s, d);
    float wt = __ldg(&w[e]);
    if ((unsigned)s >= NNODES || (unsigned)d >= NNODES) return;
    int pos = atomicAdd(&g_cursor[d], 1);
    g_adj[pos] = make_int2(s, __float_as_int(wt));
}

// ---------------------------------------------------------------------------
// Shared gather core: sum_{e in adj(n)} w_e * semb[src_e][lane], relu'd.
// ---------------------------------------------------------------------------
__device__ __forceinline__ float4 gather_row(const float4* __restrict__ semb,
                                             int node, int lane) {
    int beg = __ldg(&g_rowptr[node]);
    int end = __ldg(&g_rowptr[node + 1]);

    float4 sum = make_float4(0.f, 0.f, 0.f, 0.f);
    int i = beg;
    for (; i + 3 < end; i += 4) {
        int2 a0 = __ldg(&g_adj[i]);
        int2 a1 = __ldg(&g_adj[i + 1]);
        int2 a2 = __ldg(&g_adj[i + 2]);
        int2 a3 = __ldg(&g_adj[i + 3]);
        float4 v0 = __ldg(&semb[a0.x * 16 + lane]);
        float4 v1 = __ldg(&semb[a1.x * 16 + lane]);
        float4 v2 = __ldg(&semb[a2.x * 16 + lane]);
        float4 v3 = __ldg(&semb[a3.x * 16 + lane]);
        float w0 = __int_as_float(a0.y);
        float w1 = __int_as_float(a1.y);
        float w2 = __int_as_float(a2.y);
        float w3 = __int_as_float(a3.y);
        sum.x = fmaf(v0.x, w0, sum.x); sum.y = fmaf(v0.y, w0, sum.y);
        sum.z = fmaf(v0.z, w0, sum.z); sum.w = fmaf(v0.w, w0, sum.w);
        sum.x = fmaf(v1.x, w1, sum.x); sum.y = fmaf(v1.y, w1, sum.y);
        sum.z = fmaf(v1.z, w1, sum.z); sum.w = fmaf(v1.w, w1, sum.w);
        sum.x = fmaf(v2.x, w2, sum.x); sum.y = fmaf(v2.y, w2, sum.y);
        sum.z = fmaf(v2.z, w2, sum.z); sum.w = fmaf(v2.w, w2, sum.w);
        sum.x = fmaf(v3.x, w3, sum.x); sum.y = fmaf(v3.y, w3, sum.y);
        sum.z = fmaf(v3.z, w3, sum.z); sum.w = fmaf(v3.w, w3, sum.w);
    }
    for (; i < end; i++) {
        int2 a0 = __ldg(&g_adj[i]);
        float4 v0 = __ldg(&semb[a0.x * 16 + lane]);
        float w0 = __int_as_float(a0.y);
        sum.x = fmaf(v0.x, w0, sum.x); sum.y = fmaf(v0.y, w0, sum.y);
        sum.z = fmaf(v0.z, w0, sum.z); sum.w = fmaf(v0.w, w0, sum.w);
    }
    sum.x = fmaxf(sum.x, 0.f); sum.y = fmaxf(sum.y, 0.f);
    sum.z = fmaxf(sum.z, 0.f); sum.w = fmaxf(sum.w, 0.f);
    return sum;
}

// ---------------------------------------------------------------------------
// gather layer 1: emb_b = relu(A @ emb_a); acc += emb_b.
// ---------------------------------------------------------------------------
__global__ void gather1_kernel() {
    int t = blockIdx.x * blockDim.x + threadIdx.x;
    int node = t >> 4;
    if (node >= NNODES) return;
    int lane = t & 15;

    float4 sum = gather_row(g_emb_a, node, lane);

    int idx = node * 16 + lane;
    g_emb_b[idx] = sum;
    float4 a = g_acc[idx];
    a.x += sum.x; a.y += sum.y; a.z += sum.z; a.w += sum.w;
    g_acc[idx] = a;
}

// ---------------------------------------------------------------------------
// gather layer 2 fused with final linear:
//   e2 = relu(A @ emb_b);  row = (acc + e2) / 3;  out = row @ W^T + b
// 16 nodes per 256-thread block. No acc/emb stores — row goes through smem
// straight into the GEMV. GEMV lane mapping j = lane + 16k is smem
// bank-conflict-free on Wt.
// ---------------------------------------------------------------------------
__global__ void gather2_final_kernel(const float* __restrict__ Wm,
                                     const float* __restrict__ bias,
                                     float* __restrict__ out) {
    __shared__ float Wt[DIM][DIM + 1];    // Wt[d][j] = W[j][d]
    __shared__ float rowS[16][DIM];

    int tid = threadIdx.x;
    for (int k = tid; k < DIM * DIM; k += 256) {
        int j = k / DIM, d = k % DIM;
        Wt[d][j] = __ldg(&Wm[k]);
    }

    int nl = tid >> 4;                    // local node 0..15
    int lane = tid & 15;
    int node = blockIdx.x * 16 + nl;      // grid is exactly NNODES/16

    float4 sum = gather_row(g_emb_b, node, lane);

    float4 a = g_acc[node * 16 + lane];
    const float inv3 = 1.0f / 3.0f;
    rowS[nl][lane * 4 + 0] = (a.x + sum.x) * inv3;
    rowS[nl][lane * 4 + 1] = (a.y + sum.y) * inv3;
    rowS[nl][lane * 4 + 2] = (a.z + sum.z) * inv3;
    rowS[nl][lane * 4 + 3] = (a.w + sum.w) * inv3;
    __syncthreads();

    // GEMV: 4 outputs per thread, j = lane + 16k (conflict-free Wt reads)
    float o0 = __ldg(&bias[lane]);
    float o1 = __ldg(&bias[lane + 16]);
    float o2 = __ldg(&bias[lane + 32]);
    float o3 = __ldg(&bias[lane + 48]);
    #pragma unroll
    for (int d = 0; d < DIM; d++) {
        float rv = rowS[nl][d];
        o0 = fmaf(rv, Wt[d][lane],      o0);
        o1 = fmaf(rv, Wt[d][lane + 16], o1);
        o2 = fmaf(rv, Wt[d][lane + 32], o2);
        o3 = fmaf(rv, Wt[d][lane + 48], o3);
    }

    float* dst;
    if (node < NUSERS) {
        dst = out + (size_t)node * DIM;
    } else {
        dst = out + (size_t)2 * NUSERS * DIM + (size_t)(node - NUSERS) * DIM;
    }
    dst[lane]      = o0;
    dst[lane + 16] = o1;
    dst[lane + 32] = o2;
    dst[lane + 48] = o3;
}

// ---------------------------------------------------------------------------
extern "C" void kernel_launch(void* const* d_in, const int* in_sizes, int n_in,
                              void* d_out, int out_size) {
    const void*   ei    = d_in[0];
    const float*  w     = (const float*)d_in[1];
    const float4* users = (const float4*)d_in[2];
    const float4* items = (const float4*)d_in[3];
    const float*  Wm    = (const float*)d_in[4];
    const float*  bias  = (const float*)d_in[5];
    float* out = (float*)d_out;

    probe_kernel<<<(NNODES + 255) / 256, 256>>>((const int*)ei);

    const int nodeThreads = NNODES * 16;
    init_count_kernel<<<(nodeThreads + 255) / 256, 256>>>(users, items,
                                                          (float4*)out, ei);

    scanA_kernel<<<NBLK, SCAN_B>>>();
    scanB_kernel<<<1, 256>>>();
    scanC_kernel<<<(NNODES + 255) / 256, 256>>>();
    fill_kernel<<<(NEDGES + 255) / 256, 256>>>(ei, w);

    gather1_kernel<<<(nodeThreads + 255) / 256, 256>>>();
    gather2_final_kernel<<<NNODES / 16, 256>>>(Wm, bias, out);
}